// round 5
// baseline (speedup 1.0000x reference)
#include <cuda_runtime.h>
#include <cstdint>

#define BB 4
#define SS 1024
#define HH 32
#define DD 8
#define EE 256
constexpr int NROWS = BB * SS * HH;

// Scratch (allocation-free rule: __device__ globals)
__device__ float g_att[BB * SS * EE];       // [B,S,E] attention out, 4 MB

// ---------- packed f32x2 helpers (Blackwell dual FP32 datapath) ----------
__device__ __forceinline__ unsigned long long pack2(float lo, float hi) {
    unsigned long long r;
    asm("mov.b64 %0, {%1, %2};" : "=l"(r) : "f"(lo), "f"(hi));
    return r;
}
__device__ __forceinline__ void unpack2(unsigned long long v, float& lo, float& hi) {
    asm("mov.b64 {%0, %1}, %2;" : "=f"(lo), "=f"(hi) : "l"(v));
}
__device__ __forceinline__ unsigned long long ffma2(unsigned long long a,
                                                    unsigned long long b,
                                                    unsigned long long c) {
    unsigned long long d;
    asm("fma.rn.f32x2 %0, %1, %2, %3;" : "=l"(d) : "l"(a), "l"(b), "l"(c));
    return d;
}
__device__ __forceinline__ unsigned long long fadd2(unsigned long long a,
                                                    unsigned long long b) {
    unsigned long long d;
    asm("add.rn.f32x2 %0, %1, %2;" : "=l"(d) : "l"(a), "l"(b));
    return d;
}
__device__ __forceinline__ float ex2(float x) {
    float y;
    asm("ex2.approx.ftz.f32 %0, %1;" : "=f"(y) : "f"(x));
    return y;
}

// ---------------------------------------------------------------------------
// Fused kernel: quantum heads (closed form) + attention.
// Closed form of the circuit: after the CNOT ring,
//   <Z_w> = prod_{j=0..w} cos(x_j+theta_j) (w>=1), <Z_0> = prod_{j=1..7}.
// Each block = (head bh, query slab of 256). Phase 1 builds the full head
// K(=Q=V) tile in SMEM, pair-packed: sF[p*16 + 2d + lane] = Z[2p+lane][d]
// (32 KB). Phase 2: 128 threads x 2 queries each; lanes carry two keys,
// q broadcast into both lanes (pre-scaled by log2(e)/sqrt(8)), so an 8-step
// ffma2 chain yields two full dots, ex2 on each lane, AV accumulated in
// even/odd-key lane partials. 2 queries share every key load.
// |score| <= sqrt(8): single-pass softmax, no max subtraction.
// ---------------------------------------------------------------------------
__global__ void __launch_bounds__(128) attn_kernel(const float* __restrict__ x,
                                                   const float* __restrict__ theta) {
    __shared__ float sF[SS * 8];   // 32 KB pair-packed head tile

    int bh   = blockIdx.x;         // 0..127 (b*32 + h)
    int slab = blockIdx.y;         // 0..3
    int tid  = threadIdx.x;
    int b = bh >> 5, h = bh & 31;

    float th[8];
#pragma unroll
    for (int d = 0; d < 8; d++) th[d] = theta[d];

    // Phase 1: compute head K-tile (all 1024 rows), pair-packed into SMEM.
    for (int j = tid; j < SS; j += 128) {
        const float4* gx = reinterpret_cast<const float4*>(
            x + ((size_t)(b * SS + j) * EE + h * DD));
        float4 xa = gx[0];
        float4 xb = gx[1];

        float c[8];
        c[0] = cosf(xa.x + th[0]);
        c[1] = cosf(xa.y + th[1]);
        c[2] = cosf(xa.z + th[2]);
        c[3] = cosf(xa.w + th[3]);
        c[4] = cosf(xb.x + th[4]);
        c[5] = cosf(xb.y + th[5]);
        c[6] = cosf(xb.z + th[6]);
        c[7] = cosf(xb.w + th[7]);

        float z[8];
        float p = c[0];
#pragma unroll
        for (int w = 1; w < 8; w++) { p *= c[w]; z[w] = p; }
        float s = c[7];
#pragma unroll
        for (int w = 6; w >= 1; w--) s *= c[w];
        z[0] = s;

        int base = (j >> 1) * 16 + (j & 1);
#pragma unroll
        for (int d = 0; d < 8; d++) sF[base + 2 * d] = z[d];
    }
    __syncthreads();

    const float kS = 1.4426950408889634f / 2.8284271247461903f;  // log2(e)/sqrt(8)

    // Phase 2: two queries per thread, sharing key loads.
    int qr0 = slab * 256 + tid * 2;     // queries qr0, qr0+1

    unsigned long long q2[2][8];
#pragma unroll
    for (int q = 0; q < 2; q++) {
        int qr = qr0 + q;
#pragma unroll
        for (int d = 0; d < 8; d++) {
            float qv = sF[(qr >> 1) * 16 + 2 * d + (qr & 1)] * kS;
            q2[q][d] = pack2(qv, qv);
        }
    }

    unsigned long long o[2][8];
#pragma unroll
    for (int q = 0; q < 2; q++)
#pragma unroll
        for (int d = 0; d < 8; d++) o[q][d] = 0ULL;
    unsigned long long l2[2] = {0ULL, 0ULL};

    const ulonglong2* kp2 = reinterpret_cast<const ulonglong2*>(sF);

#pragma unroll 2
    for (int p = 0; p < SS / 2; p++) {
        ulonglong2 w01 = kp2[p * 4 + 0];
        ulonglong2 w23 = kp2[p * 4 + 1];
        ulonglong2 w45 = kp2[p * 4 + 2];
        ulonglong2 w67 = kp2[p * 4 + 3];

#pragma unroll
        for (int q = 0; q < 2; q++) {
            unsigned long long acc = ffma2(q2[q][0], w01.x, 0ULL);
            acc = ffma2(q2[q][1], w01.y, acc);
            acc = ffma2(q2[q][2], w23.x, acc);
            acc = ffma2(q2[q][3], w23.y, acc);
            acc = ffma2(q2[q][4], w45.x, acc);
            acc = ffma2(q2[q][5], w45.y, acc);
            acc = ffma2(q2[q][6], w67.x, acc);
            acc = ffma2(q2[q][7], w67.y, acc);

            float s0, s1;
            unpack2(acc, s0, s1);
            unsigned long long pp = pack2(ex2(s0), ex2(s1));   // {p(key 2p), p(key 2p+1)}

            l2[q] = fadd2(l2[q], pp);
            o[q][0] = ffma2(pp, w01.x, o[q][0]);
            o[q][1] = ffma2(pp, w01.y, o[q][1]);
            o[q][2] = ffma2(pp, w23.x, o[q][2]);
            o[q][3] = ffma2(pp, w23.y, o[q][3]);
            o[q][4] = ffma2(pp, w45.x, o[q][4]);
            o[q][5] = ffma2(pp, w45.y, o[q][5]);
            o[q][6] = ffma2(pp, w67.x, o[q][6]);
            o[q][7] = ffma2(pp, w67.y, o[q][7]);
        }
    }

#pragma unroll
    for (int q = 0; q < 2; q++) {
        float ll, lh;
        unpack2(l2[q], ll, lh);
        float inv = 1.f / (ll + lh);

        float r[8];
#pragma unroll
        for (int d = 0; d < 8; d++) {
            float lo, hi;
            unpack2(o[q][d], lo, hi);
            r[d] = (lo + hi) * inv;
        }
        float* dst = g_att + ((size_t)(b * SS + qr0 + q)) * EE + h * DD;
        *reinterpret_cast<float4*>(dst)     = make_float4(r[0], r[1], r[2], r[3]);
        *reinterpret_cast<float4*>(dst + 4) = make_float4(r[4], r[5], r[6], r[7]);
    }
}

// ---------------------------------------------------------------------------
// Kernel 3: out = g_att @ W^T.  M=4096, N=256, K=256, fp32.
// 64x64 tile, 256 threads, 4x4 micro-tile, k packed into f32x2 FMAs,
// pad-17 rows (max 2-way LDS conflict).
// ---------------------------------------------------------------------------
__global__ void gemm_kernel(const float* __restrict__ W, float* __restrict__ out) {
    __shared__ float As[64][17];
    __shared__ float Bs[64][17];

    int tx = threadIdx.x, ty = threadIdx.y;
    int tid = ty * 16 + tx;
    int m0 = blockIdx.y * 64, n0 = blockIdx.x * 64;

    unsigned long long acc2[4][4];
#pragma unroll
    for (int i = 0; i < 4; i++)
#pragma unroll
        for (int j = 0; j < 4; j++) acc2[i][j] = 0ULL;

    int lr = tid >> 2;
    int lc = (tid & 3) * 4;

    for (int k0 = 0; k0 < EE; k0 += 16) {
        float4 av = *reinterpret_cast<const float4*>(
            &g_att[(size_t)(m0 + lr) * EE + k0 + lc]);
        float4 bv = *reinterpret_cast<const float4*>(
            &W[(size_t)(n0 + lr) * EE + k0 + lc]);
        As[lr][lc] = av.x; As[lr][lc + 1] = av.y;
        As[lr][lc + 2] = av.z; As[lr][lc + 3] = av.w;
        Bs[lr][lc] = bv.x; Bs[lr][lc + 1] = bv.y;
        Bs[lr][lc + 2] = bv.z; Bs[lr][lc + 3] = bv.w;
        __syncthreads();

#pragma unroll
        for (int kk = 0; kk < 16; kk += 2) {
            unsigned long long a[4], b[4];
#pragma unroll
            for (int i = 0; i < 4; i++) {
                float x0 = As[ty * 4 + i][kk], x1 = As[ty * 4 + i][kk + 1];
                a[i] = pack2(x0, x1);
            }
#pragma unroll
            for (int j = 0; j < 4; j++) {
                float x0 = Bs[tx * 4 + j][kk], x1 = Bs[tx * 4 + j][kk + 1];
                b[j] = pack2(x0, x1);
            }
#pragma unroll
            for (int i = 0; i < 4; i++)
#pragma unroll
                for (int j = 0; j < 4; j++)
                    acc2[i][j] = ffma2(a[i], b[j], acc2[i][j]);
        }
        __syncthreads();
    }

#pragma unroll
    for (int i = 0; i < 4; i++) {
        float v[4];
#pragma unroll
        for (int j = 0; j < 4; j++) {
            float lo, hi;
            unpack2(acc2[i][j], lo, hi);
            v[j] = lo + hi;
        }
        *reinterpret_cast<float4*>(&out[(size_t)(m0 + ty * 4 + i) * EE + n0 + tx * 4]) =
            make_float4(v[0], v[1], v[2], v[3]);
    }
}

// ---------------------------------------------------------------------------
extern "C" void kernel_launch(void* const* d_in, const int* in_sizes, int n_in,
                              void* d_out, int out_size) {
    const float* x = nullptr;
    const float* theta = nullptr;
    const float* w = nullptr;
    for (int i = 0; i < n_in; i++) {
        if (in_sizes[i] == NROWS * DD)      x = (const float*)d_in[i];
        else if (in_sizes[i] == DD)         theta = (const float*)d_in[i];
        else if (in_sizes[i] == EE * EE)    w = (const float*)d_in[i];
    }

    attn_kernel<<<dim3(BB * HH, 4), 128>>>(x, theta);
    gemm_kernel<<<dim3(EE / 64, BB * SS / 64), dim3(16, 16)>>>(w, (float*)d_out);
}